// round 14
// baseline (speedup 1.0000x reference)
#include <cuda_runtime.h>
#include <cuda_bf16.h>
#include <cstdint>

// Math (first-order collapse of 19 gradient steps, validated):
//   a0    = x @ phi
//   resid = a0 @ phi^T - x
//   out   = a0 - C19 * (resid @ phi + sm * sign(a0)),  C19 = 19*0.005/256
//
// R14: CTA-level split-K (gridDim.z = 2). R12 showed intra-CTA warps stall
// together (shared barrier/tiles); independent CTAs interleave stalls. Each
// half-K CTA writes fp32 partials; combine kernels fuse p0+p1 + epilogue.
// GEMM1 accuracy: bf16 hi/lo split via K-concat (K=9216):
//   A1 = [xh | xh | xl],  B1 = [phT | plT | phT]  ->  xh*ph + xh*pl + xl*ph

#define DINL __device__ __forceinline__

// ---------------- scratch (device globals; no allocation allowed) -----------
__device__ __align__(1024) __nv_bfloat16 g_A1[256 * 9216];   // 4.7 MB
__device__ __align__(1024) __nv_bfloat16 g_B1[4096 * 9216];  // 75.5 MB
__device__ __align__(1024) __nv_bfloat16 g_B2[3072 * 4096];  // 25.2 MB
__device__ __align__(1024) float         g_a0f[256 * 4096];  // 4.2 MB
__device__ __align__(1024) __nv_bfloat16 g_a0h[256 * 4096];  // 2.1 MB
__device__ __align__(1024) __nv_bfloat16 g_rh[256 * 3072];   // 1.6 MB
__device__ __align__(1024) float         g_part[2 * 256 * 4096];  // 8.4 MB partials

// ---------------- PTX helpers -----------------------------------------------
DINL uint32_t smem_u32(const void* p) {
    uint32_t a;
    asm("{ .reg .u64 t; cvta.to.shared.u64 t, %1; cvt.u32.u64 %0, t; }"
        : "=r"(a) : "l"(p));
    return a;
}

#define CP16(dst, src) \
    asm volatile("cp.async.cg.shared.global [%0], [%1], 16;" :: "r"(dst), "l"(src) : "memory")
#define CP_COMMIT() asm volatile("cp.async.commit_group;" ::: "memory")
#define CP_WAIT2()  asm volatile("cp.async.wait_group 2;" ::: "memory")

#define LDSM4(r0, r1, r2, r3, addr) \
    asm volatile("ldmatrix.sync.aligned.m8n8.x4.shared.b16 {%0,%1,%2,%3}, [%4];" \
        : "=r"(r0), "=r"(r1), "=r"(r2), "=r"(r3) : "r"(addr))

DINL void mma16(float& d0, float& d1, float& d2, float& d3,
                uint32_t a0, uint32_t a1, uint32_t a2, uint32_t a3,
                uint32_t b0, uint32_t b1) {
    asm volatile(
        "mma.sync.aligned.m16n8k16.row.col.f32.bf16.bf16.f32 "
        "{%0,%1,%2,%3}, {%4,%5,%6,%7}, {%8,%9}, {%0,%1,%2,%3};"
        : "+f"(d0), "+f"(d1), "+f"(d2), "+f"(d3)
        : "r"(a0), "r"(a1), "r"(a2), "r"(a3), "r"(b0), "r"(b1));
}

DINL uint32_t pack2(float a, float b) {
    __nv_bfloat162 t = __floats2bfloat162_rn(a, b);
    return *reinterpret_cast<uint32_t*>(&t);
}

// ---------------- conversion kernels -----------------------------------------
__global__ __launch_bounds__(256) void conv_x(const float* __restrict__ x,
                                              __nv_bfloat16* __restrict__ A1) {
    int t = blockIdx.x * 256 + threadIdx.x;  // 256*3072 elements
    int m = t / 3072;
    int k = t - m * 3072;
    float f = x[t];
    __nv_bfloat16 h = __float2bfloat16(f);
    __nv_bfloat16 l = __float2bfloat16(f - __bfloat162float(h));
    size_t base = (size_t)m * 9216 + k;
    A1[base] = h;          // pairs with phT
    A1[base + 3072] = h;   // pairs with plT
    A1[base + 6144] = l;   // pairs with phT
}

// tile: 64 pixels (p) x 32 neurons (n), 512 threads
__global__ __launch_bounds__(512) void conv_phi(const float* __restrict__ phi,
                                                __nv_bfloat16* __restrict__ B1,
                                                __nv_bfloat16* __restrict__ B2) {
    __shared__ float tile[64][33];
    int p0 = blockIdx.y * 64, n0 = blockIdx.x * 32;
    int tx = threadIdx.x & 31, ty = threadIdx.x >> 5;  // ty 0..15
#pragma unroll
    for (int r = 0; r < 4; r++) {
        int pl = ty + 16 * r;
        float f = phi[(size_t)(p0 + pl) * 4096 + n0 + tx];
        tile[pl][tx] = f;
        B2[(size_t)(p0 + pl) * 4096 + n0 + tx] = __float2bfloat16(f);
    }
    __syncthreads();
    int pl2 = threadIdx.x & 63, nl2 = threadIdx.x >> 6;  // nl2 0..7
#pragma unroll
    for (int r = 0; r < 4; r++) {
        int nl = nl2 + 8 * r;
        float f = tile[pl2][nl];
        __nv_bfloat16 h = __float2bfloat16(f);
        __nv_bfloat16 l = __float2bfloat16(f - __bfloat162float(h));
        size_t base = (size_t)(n0 + nl) * 9216 + p0 + pl2;
        B1[base] = h;          // phT
        B1[base + 3072] = l;   // plT
        B1[base + 6144] = h;   // phT (pairs with xl)
    }
}

// ---------------- bf16 tensor-core GEMM (split-K partial) --------------------
// P[z] += A[m, zKper:(z+1)Kper] * B[n, ...].  BM=64, BN=64, BK=32.
// 128 threads = 4 warps (2M x 2N); warp tile 32x32.
// 4-stage cp.async ring (prefetch distance 3), ONE __syncthreads per iter.
// gridDim.z = KSPLIT; writes fp32 partial to P + z*MN.

constexpr int SAu = 20;             // u32 row stride (16 data + 4 pad)
constexpr int STG = 64 * SAu;       // 1280 u32 per operand per stage

__global__ __launch_bounds__(128) void gemm_part(
    const __nv_bfloat16* __restrict__ A, const __nv_bfloat16* __restrict__ B,
    float* __restrict__ P, int Kper, int lda, int ldb, int ldc, int MN)
{
    __shared__ uint32_t As[4 * STG];
    __shared__ uint32_t Bs[4 * STG];
    const uint32_t sA_u = smem_u32(As);
    const uint32_t sB_u = smem_u32(Bs);

    const int tid = threadIdx.x, lane = tid & 31, wid = tid >> 5;
    const int wm = wid >> 1, wn = wid & 1;     // 2 x 2 warps
    const int m0 = blockIdx.y * 64, n0 = blockIdx.x * 64;
    const int z = blockIdx.z;
    const int g = lane >> 2, c4 = lane & 3;

    // bias operand pointers to this CTA's K range (K is the contiguous dim)
    A += (size_t)z * Kper;
    B += (size_t)z * Kper;

    // ldmatrix lane offsets (bytes)
    const int j = lane >> 3, r8 = lane & 7;
    const uint32_t aoffB = (uint32_t)(((j & 1) * 8 + r8) * SAu + (j >> 1) * 4) * 4;
    const uint32_t boffB = (uint32_t)(r8 * SAu + (j & 1) * 4 + (j >> 1) * 8) * 4;

    float acc[2][4][4];
#pragma unroll
    for (int mt = 0; mt < 2; mt++)
#pragma unroll
        for (int nt = 0; nt < 4; nt++)
#pragma unroll
            for (int r = 0; r < 4; r++) acc[mt][nt][r] = 0.0f;

    const int nk = Kper >> 5;   // BK = 32 bf16

    auto load_tile = [&](int t, int slot) {
        const char* Ab = (const char*)A + ((size_t)m0 * lda + t * 32) * 2;
        uint32_t ad = sA_u + slot * STG * 4;
#pragma unroll
        for (int h = 0; h < 2; h++) {
            int idx = tid + h * 128;
            int row = idx >> 2, seg = idx & 3;
            CP16(ad + (uint32_t)(row * SAu + seg * 4) * 4,
                 Ab + (size_t)row * lda * 2 + seg * 16);
        }
        const char* Bb = (const char*)B + ((size_t)n0 * ldb + t * 32) * 2;
        uint32_t bd = sB_u + slot * STG * 4;
#pragma unroll
        for (int h = 0; h < 2; h++) {
            int idx = tid + h * 128;
            int row = idx >> 2, seg = idx & 3;
            CP16(bd + (uint32_t)(row * SAu + seg * 4) * 4,
                 Bb + (size_t)row * ldb * 2 + seg * 16);
        }
    };

    load_tile(0, 0); CP_COMMIT();
    load_tile(1, 1); CP_COMMIT();
    load_tile(2, 2); CP_COMMIT();

    for (int i = 0; i < nk; i++) {
        CP_WAIT2();            // tile i resident
        __syncthreads();
        if (i + 3 < nk) load_tile(i + 3, (i + 3) & 3);
        CP_COMMIT();           // always commit -> group index == tile index

        const uint32_t aBase = sA_u + ((i & 3) * STG + (wm * 32) * SAu) * 4 + aoffB;
        const uint32_t bBase = sB_u + ((i & 3) * STG + (wn * 32) * SAu) * 4 + boffB;

        // batch ALL fragment loads first (8 LDSM.x4), then 16 HMMA
        uint32_t bb[4][2][2];   // [nt][ks][2]
#pragma unroll
        for (int nt = 0; nt < 4; nt++) {
            uint32_t ba = bBase + (uint32_t)(nt * 8 * SAu) * 4;
            LDSM4(bb[nt][0][0], bb[nt][0][1], bb[nt][1][0], bb[nt][1][1], ba);
        }
        uint32_t aa[2][2][4];   // [ks][mt][4]
#pragma unroll
        for (int ks = 0; ks < 2; ks++)
#pragma unroll
            for (int mt = 0; mt < 2; mt++) {
                uint32_t aaddr = aBase + (uint32_t)(mt * 16 * SAu + ks * 8) * 4;
                LDSM4(aa[ks][mt][0], aa[ks][mt][1], aa[ks][mt][2], aa[ks][mt][3], aaddr);
            }
#pragma unroll
        for (int ks = 0; ks < 2; ks++)
#pragma unroll
            for (int mt = 0; mt < 2; mt++)
#pragma unroll
                for (int nt = 0; nt < 4; nt++)
                    mma16(acc[mt][nt][0], acc[mt][nt][1], acc[mt][nt][2], acc[mt][nt][3],
                          aa[ks][mt][0], aa[ks][mt][1], aa[ks][mt][2], aa[ks][mt][3],
                          bb[nt][ks][0], bb[nt][ks][1]);
    }

    // ---- write fp32 partial ----
    float* Pz = P + (size_t)z * MN;
#pragma unroll
    for (int mt = 0; mt < 2; mt++) {
        const int r0 = m0 + wm * 32 + mt * 16 + g;
#pragma unroll
        for (int nt = 0; nt < 4; nt++) {
            const int col = n0 + wn * 32 + nt * 8 + 2 * c4;
#pragma unroll
            for (int half = 0; half < 2; half++) {
                const int row = r0 + half * 8;
                float2 v = {acc[mt][nt][half * 2 + 0], acc[mt][nt][half * 2 + 1]};
                *reinterpret_cast<float2*>(&Pz[(size_t)row * ldc + col]) = v;
            }
        }
    }
}

// ---------------- combine kernels (p0 + p1 + epilogue) -----------------------
__global__ __launch_bounds__(256) void combine1(const float* __restrict__ P,
                                                float* __restrict__ a0f,
                                                __nv_bfloat16* __restrict__ a0h,
                                                int MN) {
    int i = blockIdx.x * 256 + threadIdx.x;           // float4 index
    const float4 p0 = reinterpret_cast<const float4*>(P)[i];
    const float4 p1 = reinterpret_cast<const float4*>(P + MN)[i];
    float4 s = {p0.x + p1.x, p0.y + p1.y, p0.z + p1.z, p0.w + p1.w};
    reinterpret_cast<float4*>(a0f)[i] = s;
    uint2 pk = {pack2(s.x, s.y), pack2(s.z, s.w)};
    reinterpret_cast<uint2*>(a0h)[i] = pk;
}

__global__ __launch_bounds__(256) void combine2(const float* __restrict__ P,
                                                const float* __restrict__ x,
                                                __nv_bfloat16* __restrict__ rh,
                                                int MN) {
    int i = blockIdx.x * 256 + threadIdx.x;
    const float4 p0 = reinterpret_cast<const float4*>(P)[i];
    const float4 p1 = reinterpret_cast<const float4*>(P + MN)[i];
    const float4 xv = reinterpret_cast<const float4*>(x)[i];
    uint2 pk = {pack2(p0.x + p1.x - xv.x, p0.y + p1.y - xv.y),
                pack2(p0.z + p1.z - xv.z, p0.w + p1.w - xv.w)};
    reinterpret_cast<uint2*>(rh)[i] = pk;
}

__global__ __launch_bounds__(256) void combine3(const float* __restrict__ P,
                                                const float* __restrict__ a0f,
                                                const float* __restrict__ SMP,
                                                float* __restrict__ out,
                                                int MN) {
    const float c19 = 19.0f * (0.005f / 256.0f);
    const float smv = SMP[0];
    int i = blockIdx.x * 256 + threadIdx.x;
    const float4 p0 = reinterpret_cast<const float4*>(P)[i];
    const float4 p1 = reinterpret_cast<const float4*>(P + MN)[i];
    const float4 av = reinterpret_cast<const float4*>(a0f)[i];
    float4 o;
    float s0 = (av.x > 0.f) ? 1.f : ((av.x < 0.f) ? -1.f : 0.f);
    float s1 = (av.y > 0.f) ? 1.f : ((av.y < 0.f) ? -1.f : 0.f);
    float s2 = (av.z > 0.f) ? 1.f : ((av.z < 0.f) ? -1.f : 0.f);
    float s3 = (av.w > 0.f) ? 1.f : ((av.w < 0.f) ? -1.f : 0.f);
    o.x = av.x - c19 * (p0.x + p1.x + smv * s0);
    o.y = av.y - c19 * (p0.y + p1.y + smv * s1);
    o.z = av.z - c19 * (p0.z + p1.z + smv * s2);
    o.w = av.w - c19 * (p0.w + p1.w + smv * s3);
    reinterpret_cast<float4*>(out)[i] = o;
}

// ---------------- launch -----------------------------------------------------
extern "C" void kernel_launch(void* const* d_in, const int* in_sizes, int n_in,
                              void* d_out, int out_size)
{
    const float* x   = (const float*)d_in[0];  // [256, 3072]
    const float* phi = (const float*)d_in[1];  // [3072, 4096]
    const float* smp = (const float*)d_in[2];  // scalar
    float* out = (float*)d_out;                // [256, 4096]

    __nv_bfloat16 *A1, *B1, *B2, *a0h, *rh;
    float *a0f, *part;
    cudaGetSymbolAddress((void**)&A1, g_A1);
    cudaGetSymbolAddress((void**)&B1, g_B1);
    cudaGetSymbolAddress((void**)&B2, g_B2);
    cudaGetSymbolAddress((void**)&a0f, g_a0f);
    cudaGetSymbolAddress((void**)&a0h, g_a0h);
    cudaGetSymbolAddress((void**)&rh, g_rh);
    cudaGetSymbolAddress((void**)&part, g_part);

    const int MN1 = 256 * 4096;   // 1,048,576
    const int MN2 = 256 * 3072;   //   786,432

    // conversions
    conv_x<<<(256 * 3072) / 256, 256>>>(x, A1);
    conv_phi<<<dim3(4096 / 32, 3072 / 64), 512>>>(phi, B1, B2);

    // GEMM1: a0 = A1 @ B1^T   M=256, N=4096, K=9216, split-K 2
    gemm_part<<<dim3(4096 / 64, 4, 2), 128>>>(
        A1, B1, part, 4608, 9216, 9216, 4096, MN1);
    combine1<<<MN1 / 1024, 256>>>(part, a0f, a0h, MN1);

    // GEMM2: resid = a0h @ B2^T - x   M=256, N=3072, K=4096, split-K 2
    gemm_part<<<dim3(3072 / 64, 4, 2), 128>>>(
        a0h, B2, part, 2048, 4096, 4096, 3072, MN2);
    combine2<<<MN2 / 1024, 256>>>(part, x, rh, MN2);

    // GEMM3: out = a0f - c19*(rh @ phT^T + sm*sign(a0f))  M=256, N=4096, K=3072, split-K 2
    gemm_part<<<dim3(4096 / 64, 4, 2), 128>>>(
        rh, B1, part, 1536, 3072, 9216, 4096, MN1);
    combine3<<<MN1 / 1024, 256>>>(part, a0f, smp, out, MN1);
}